// round 16
// baseline (speedup 1.0000x reference)
#include <cuda_runtime.h>
#include <cstdint>
#include <cstddef>

// Problem constants
#define BB 4
#define SS 2048
#define DD 1024
#define HH 16
#define LL 8
#define VV 8192
#define HDIM 64
#define MTOK (BB*SS)   // 8192 tokens

typedef unsigned long long ull;

// ---------------------------------------------------------------------------
// Static device scratch (no allocations allowed)
// ---------------------------------------------------------------------------
__device__ float g_x   [(size_t)MTOK * DD];        // residual fp32        32MB
__device__ float g_qkv [(size_t)MTOK * 3 * DD];    // qkv fp32             96MB
__device__ float g_attn[(size_t)MTOK * DD];        // attn out fp32        32MB
__device__ float g_fc  [(size_t)MTOK * 4 * DD];    // fc out fp32         128MB
__device__ __align__(16) char g_xah[(size_t)MTOK * 4 * DD];  // act hi int8 32MB
__device__ __align__(16) char g_xal[(size_t)MTOK * 4 * DD];  // act lo int8 32MB
__device__ __align__(16) char g_wh [(size_t)VV * DD];        // wgt hi int8  8MB
__device__ __align__(16) char g_wl [(size_t)VV * DD];        // wgt lo int8  8MB
__device__ float g_sa[MTOK];                       // act row scales
__device__ float g_sw[VV];                         // weight row scales

// ---------------------------------------------------------------------------
// Helpers
// ---------------------------------------------------------------------------
__device__ __forceinline__ float gelu_f(float x) {
    float z = 0.7978845608028654f * (x + 0.044715f * x * x * x);
    float e = __expf(2.0f * z);
    float th = 1.0f - 2.0f / (e + 1.0f);
    return 0.5f * x * (1.0f + th);
}

// bf16 helpers (attention-internal only)
__device__ __forceinline__ uint32_t bf2(float lo, float hi) {
    uint32_t r; asm("cvt.rn.bf16x2.f32 %0, %1, %2;" : "=r"(r) : "f"(hi), "f"(lo)); return r;
}
__device__ __forceinline__ void split2(float x, float y, uint32_t& hi, uint32_t& lo) {
    hi = bf2(x, y);
    float rx = x - __uint_as_float(hi << 16);
    float ry = y - __uint_as_float(hi & 0xffff0000u);
    lo = bf2(rx, ry);
}

__device__ __forceinline__ uint32_t smem_u32(const void* p) {
    uint32_t a;
    asm("{ .reg .u64 t; cvta.to.shared.u64 t, %1; cvt.u32.u64 %0, t; }" : "=r"(a) : "l"(p));
    return a;
}

// ---------------------------------------------------------------------------
// mma.sync / ldmatrix / cp.async (sm_80-compatible path)
// ---------------------------------------------------------------------------
__device__ __forceinline__ void ldsm4(uint32_t* r, uint32_t addr) {
    asm volatile("ldmatrix.sync.aligned.m8n8.x4.shared.b16 {%0,%1,%2,%3}, [%4];"
        : "=r"(r[0]), "=r"(r[1]), "=r"(r[2]), "=r"(r[3]) : "r"(addr));
}
// bf16 MMA (attention)
__device__ __forceinline__ void mma16816(float* c, const uint32_t* a, const uint32_t* b) {
    asm volatile(
        "mma.sync.aligned.m16n8k16.row.col.f32.bf16.bf16.f32 "
        "{%0,%1,%2,%3}, {%4,%5,%6,%7}, {%8,%9}, {%0,%1,%2,%3};"
        : "+f"(c[0]), "+f"(c[1]), "+f"(c[2]), "+f"(c[3])
        : "r"(a[0]), "r"(a[1]), "r"(a[2]), "r"(a[3]), "r"(b[0]), "r"(b[1]));
}
// int8 IMMA k32 (GEMM)
__device__ __forceinline__ void imma16832(int* c, const uint32_t* a, const uint32_t* b) {
    asm volatile(
        "mma.sync.aligned.m16n8k32.row.col.s32.s8.s8.s32 "
        "{%0,%1,%2,%3}, {%4,%5,%6,%7}, {%8,%9}, {%0,%1,%2,%3};"
        : "+r"(c[0]), "+r"(c[1]), "+r"(c[2]), "+r"(c[3])
        : "r"(a[0]), "r"(a[1]), "r"(a[2]), "r"(a[3]), "r"(b[0]), "r"(b[1]));
}
__device__ __forceinline__ void cpa16(uint32_t dst, const void* src) {
    size_t g = __cvta_generic_to_global(src);
    asm volatile("cp.async.cg.shared.global [%0], [%1], 16;" :: "r"(dst), "l"(g) : "memory");
}
#define CPA_COMMIT() asm volatile("cp.async.commit_group;" ::: "memory")
#define CPA_WAIT1()  asm volatile("cp.async.wait_group 1;"  ::: "memory")

// fp32x4 -> bf16 hi/lo (attention smem tiles)
__device__ __forceinline__ void cvt_store(void* hi, void* lo, float4 v) {
    uint32_t h0 = bf2(v.x, v.y);
    uint32_t h1 = bf2(v.z, v.w);
    float bx = __uint_as_float(h0 << 16);
    float by = __uint_as_float(h0 & 0xffff0000u);
    float bz = __uint_as_float(h1 << 16);
    float bw = __uint_as_float(h1 & 0xffff0000u);
    uint32_t l0 = bf2(v.x - bx, v.y - by);
    uint32_t l1 = bf2(v.z - bz, v.w - bw);
    *(ull*)hi = ((ull)h1 << 32) | h0;
    *(ull*)lo = ((ull)l1 << 32) | l0;
}

// ---------------------------------------------------------------------------
// Unified per-row int8 split quantizer: X[row][0..W) fp32 ->
// hi/lo int8 planes (pitch W) + per-row scale. W in {1024, 4096}.
// xq = x*127/max; H = rint(xq); L = rint((xq-H)*128); x ~= s*(H + L/128)
// ---------------------------------------------------------------------------
__global__ void cvt_a(const float* __restrict__ X, char* __restrict__ oh,
                      char* __restrict__ ol, float* __restrict__ sc, int W) {
    int row = blockIdx.x, t = threadIdx.x;
    const float4* src = (const float4*)(X + (size_t)row * W);
    int nv = W >> 10;            // float4s per thread: 1 (W=1024) or 4 (W=4096)
    float4 v[4];
    float mx = 0.f;
    for (int i = 0; i < nv; i++) {
        v[i] = src[t + (i << 8)];
        mx = fmaxf(mx, fmaxf(fmaxf(fabsf(v[i].x), fabsf(v[i].y)),
                             fmaxf(fabsf(v[i].z), fabsf(v[i].w))));
    }
    #pragma unroll
    for (int o = 16; o; o >>= 1) mx = fmaxf(mx, __shfl_xor_sync(0xffffffffu, mx, o));
    __shared__ float sm8[8];
    __shared__ float sMx;
    if ((t & 31) == 0) sm8[t >> 5] = mx;
    __syncthreads();
    if (t == 0) {
        float m = 0.f;
        #pragma unroll
        for (int i = 0; i < 8; i++) m = fmaxf(m, sm8[i]);
        m = fmaxf(m, 1e-20f);
        sMx = m;
        sc[row] = m * (1.0f / 127.0f);
    }
    __syncthreads();
    float inv = 127.0f / sMx;
    uint32_t* oh4 = (uint32_t*)(oh + (size_t)row * W);
    uint32_t* ol4 = (uint32_t*)(ol + (size_t)row * W);
    for (int i = 0; i < nv; i++) {
        const float* f = (const float*)&v[i];
        uint32_t hp = 0, lp = 0;
        #pragma unroll
        for (int e = 0; e < 4; e++) {
            float q = f[e] * inv;
            int hh = __float2int_rn(q);
            int ll = __float2int_rn((q - (float)hh) * 128.0f);
            hp |= (uint32_t)(hh & 255) << (e * 8);
            lp |= (uint32_t)(ll & 255) << (e * 8);
        }
        oh4[t + (i << 8)] = hp;
        ol4[t + (i << 8)] = lp;
    }
}

// ---------------------------------------------------------------------------
// Embedding
// ---------------------------------------------------------------------------
__global__ void embed_k(const int* __restrict__ idx, const float* __restrict__ wte,
                        const float* __restrict__ wpe, float* __restrict__ x) {
    int row = blockIdx.x;
    int s   = row & (SS - 1);
    int t   = threadIdx.x;
    int tok = idx[row];
    float4 a = ((const float4*)(wte + (size_t)tok * DD))[t];
    float4 p = ((const float4*)(wpe + (size_t)s * DD))[t];
    ((float4*)(x + (size_t)row * DD))[t] =
        make_float4(a.x + p.x, a.y + p.y, a.z + p.z, a.w + p.w);
}

// ---------------------------------------------------------------------------
// LayerNorm -> fused per-row int8 split output (GEMM A operand, W=DD)
// ---------------------------------------------------------------------------
__global__ void ln_k(const float* __restrict__ x, const float* __restrict__ w,
                     const float* __restrict__ b, char* __restrict__ ohi,
                     char* __restrict__ olo, float* __restrict__ sc) {
    int row = blockIdx.x;
    int t   = threadIdx.x;
    float4 v = ((const float4*)(x + (size_t)row * DD))[t];
    float s = v.x + v.y + v.z + v.w;
    float q = v.x * v.x + v.y * v.y + v.z * v.z + v.w * v.w;
    #pragma unroll
    for (int off = 16; off; off >>= 1) {
        s += __shfl_xor_sync(0xffffffffu, s, off);
        q += __shfl_xor_sync(0xffffffffu, q, off);
    }
    __shared__ float ss[8], sq[8], sm8[8];
    __shared__ float smu, srs, sMx;
    int wid = t >> 5;
    if ((t & 31) == 0) { ss[wid] = s; sq[wid] = q; }
    __syncthreads();
    if (t == 0) {
        float S = 0.f, Q = 0.f;
        #pragma unroll
        for (int i = 0; i < 8; i++) { S += ss[i]; Q += sq[i]; }
        float mu  = S * (1.0f / DD);
        float var = Q * (1.0f / DD) - mu * mu;
        smu = mu;
        srs = rsqrtf(var + 1e-5f);
    }
    __syncthreads();
    float mu = smu, r = srs;
    float4 wv = ((const float4*)w)[t];
    float4 bv = ((const float4*)b)[t];
    float4 out;
    out.x = (v.x - mu) * r * wv.x + bv.x;
    out.y = (v.y - mu) * r * wv.y + bv.y;
    out.z = (v.z - mu) * r * wv.z + bv.z;
    out.w = (v.w - mu) * r * wv.w + bv.w;
    // row absmax reduce
    float mx = fmaxf(fmaxf(fabsf(out.x), fabsf(out.y)),
                     fmaxf(fabsf(out.z), fabsf(out.w)));
    #pragma unroll
    for (int off = 16; off; off >>= 1) mx = fmaxf(mx, __shfl_xor_sync(0xffffffffu, mx, off));
    if ((t & 31) == 0) sm8[wid] = mx;
    __syncthreads();
    if (t == 0) {
        float m = 0.f;
        #pragma unroll
        for (int i = 0; i < 8; i++) m = fmaxf(m, sm8[i]);
        m = fmaxf(m, 1e-20f);
        sMx = m;
        sc[row] = m * (1.0f / 127.0f);
    }
    __syncthreads();
    float inv = 127.0f / sMx;
    const float* f = (const float*)&out;
    uint32_t hp = 0, lp = 0;
    #pragma unroll
    for (int e = 0; e < 4; e++) {
        float qq = f[e] * inv;
        int hh = __float2int_rn(qq);
        int ll = __float2int_rn((qq - (float)hh) * 128.0f);
        hp |= (uint32_t)(hh & 255) << (e * 8);
        lp |= (uint32_t)(ll & 255) << (e * 8);
    }
    ((uint32_t*)(ohi + (size_t)row * DD))[t] = hp;
    ((uint32_t*)(olo + (size_t)row * DD))[t] = lp;
}

// ---------------------------------------------------------------------------
// int8 3-term NT GEMM: C = sa[m]*sw[n]*(Ah*Bh + (Ah*Bl + Al*Bh)/128).
// CTA 128x128, K-step 64 (2x k32 IMMA), 3-stage cp.async (32KB/stage).
// s8-k32 fragments == fp16-k16 fragments at b16-unit granularity, so all
// ldsm addressing/swizzle/repack is carried over from the proven fp16 path.
// EPI: 0 = fp32 +bias, 1 = gelu(+bias) fp32, 2 = fp32 += acc+bias, 3 = plain
// ---------------------------------------------------------------------------
#define STAGE 32768
#define PL_AH 0
#define PL_AL 8192
#define PL_BH 16384
#define PL_BL 24576
#define GEMM_SMEM (3*STAGE)

template<int EPI>
__global__ void __launch_bounds__(256, 1)
gemm_i8(const char* __restrict__ Ah, const char* __restrict__ Al,
        const char* __restrict__ Bh, const char* __restrict__ Bl,
        const float* __restrict__ sa, const float* __restrict__ sw,
        const float* __restrict__ bias, float* __restrict__ C,
        int M, int N, int K)
{
    extern __shared__ __align__(16) char sm[];
    int tid  = threadIdx.x;
    int lane = tid & 31;
    int w    = tid >> 5;
    int wm   = w & 1;
    int wn   = w >> 1;
    int bn = blockIdx.x << 7, bm = blockIdx.y << 7;
    uint32_t smb = smem_u32(sm);

    int acch[4][4][4], accm[4][4][4];
    #pragma unroll
    for (int i = 0; i < 4; i++)
        #pragma unroll
        for (int j = 0; j < 4; j++)
            #pragma unroll
            for (int r = 0; r < 4; r++) { acch[i][j][r] = 0; accm[i][j][r] = 0; }

    int nk = K >> 6;              // 64 int8 per k-step
    int lr = tid >> 1;            // tile row 0..127
    int q0 = (tid & 1) << 1;      // 16B chunk base 0 or 2
    size_t arow = (size_t)(bm + lr) * K;   // byte offsets (int8)
    size_t brow = (size_t)(bn + lr) * K;
    int swz = (lr >> 1) & 3;

    auto fill = [&](int slot, int ks) {
        int kc = ks << 6;
        uint32_t sb = smb + slot * STAGE + lr * 64;
        #pragma unroll
        for (int c = 0; c < 2; c++) {
            int q = q0 + c;
            uint32_t d = sb + ((q ^ swz) << 4);
            size_t ao = arow + kc + q * 16;
            size_t bo = brow + kc + q * 16;
            cpa16(d + PL_AH, Ah + ao);
            cpa16(d + PL_AL, Al + ao);
            cpa16(d + PL_BH, Bh + bo);
            cpa16(d + PL_BL, Bl + bo);
        }
    };
    fill(0, 0); CPA_COMMIT();
    fill(1, 1); CPA_COMMIT();

    for (int t = 0; t < nk; t++) {
        CPA_WAIT1();
        __syncthreads();
        if (t + 2 < nk) fill((t + 2) % 3, t + 2);
        CPA_COMMIT();

        uint32_t base = smb + (t % 3) * STAGE;
        #pragma unroll
        for (int kh = 0; kh < 2; kh++) {          // two k32 IMMAs per 64B row
            int cch = kh * 2 + (lane >> 4);
            uint32_t ahf[4][4], alf[4][4];
            #pragma unroll
            for (int mi = 0; mi < 4; mi++) {
                int row = wm * 64 + mi * 16 + (lane & 15);
                uint32_t ad = base + row * 64 + ((cch ^ ((row >> 1) & 3)) << 4);
                ldsm4(ahf[mi], ad + PL_AH);
                ldsm4(alf[mi], ad + PL_AL);
            }
            uint32_t bhq[2][4], blq[2][4];
            #pragma unroll
            for (int np = 0; np < 2; np++) {
                int row = wn * 32 + np * 16 + (lane & 15);
                uint32_t bd = base + row * 64 + ((cch ^ ((row >> 1) & 3)) << 4);
                ldsm4(bhq[np], bd + PL_BH);
                ldsm4(blq[np], bd + PL_BL);
            }
            uint32_t bhf[4][2], blf[4][2];
            #pragma unroll
            for (int np = 0; np < 2; np++)
                #pragma unroll
                for (int sdx = 0; sdx < 2; sdx++) {
                    bhf[np * 2 + sdx][0] = bhq[np][sdx];
                    bhf[np * 2 + sdx][1] = bhq[np][sdx + 2];
                    blf[np * 2 + sdx][0] = blq[np][sdx];
                    blf[np * 2 + sdx][1] = blq[np][sdx + 2];
                }
            #pragma unroll
            for (int mi = 0; mi < 4; mi++)
                #pragma unroll
                for (int ni = 0; ni < 4; ni++)
                    imma16832(acch[mi][ni], ahf[mi], bhf[ni]);
            #pragma unroll
            for (int mi = 0; mi < 4; mi++)
                #pragma unroll
                for (int ni = 0; ni < 4; ni++)
                    imma16832(accm[mi][ni], ahf[mi], blf[ni]);
            #pragma unroll
            for (int mi = 0; mi < 4; mi++)
                #pragma unroll
                for (int ni = 0; ni < 4; ni++)
                    imma16832(accm[mi][ni], alf[mi], bhf[ni]);
        }
    }

    // Epilogue
    int rbase = bm + wm * 64 + (lane >> 2);
    int cbase = bn + wn * 32 + ((lane & 3) << 1);
    #pragma unroll
    for (int mi = 0; mi < 4; mi++) {
        #pragma unroll
        for (int half = 0; half < 2; half++) {
            int row = rbase + mi * 16 + half * 8;
            float sr = sa[row];
            #pragma unroll
            for (int ni = 0; ni < 4; ni++) {
                int col = cbase + ni * 8;
                float s0 = sr * sw[col], s1 = sr * sw[col + 1];
                float vx = ((float)acch[mi][ni][half * 2] +
                            (float)accm[mi][ni][half * 2] * 0.0078125f) * s0;
                float vy = ((float)acch[mi][ni][half * 2 + 1] +
                            (float)accm[mi][ni][half * 2 + 1] * 0.0078125f) * s1;
                if (EPI != 3) { vx += bias[col]; vy += bias[col + 1]; }
                if (EPI == 1) { vx = gelu_f(vx); vy = gelu_f(vy); }
                float* cp = C + (size_t)row * N + col;
                if (EPI == 2) {
                    float2 o = *(const float2*)cp;
                    vx += o.x; vy += o.y;
                }
                *(float2*)cp = make_float2(vx, vy);
            }
        }
    }
}

// ---------------------------------------------------------------------------
// Tensor-core flash attention (causal), bf16x3 internal (proven R12 body);
// output written as plain fp32 to g_attn (quantized afterwards by cvt_a).
// ---------------------------------------------------------------------------
__global__ __launch_bounds__(128) void attn_k(const float* __restrict__ qkv,
                                              float* __restrict__ out) {
    __shared__ __align__(16) char KsH[8192];
    __shared__ __align__(16) char KsL[8192];
    __shared__ __align__(16) char VtH[8192];
    __shared__ __align__(16) char VtL[8192];

    int b = blockIdx.z, h = blockIdx.y, qt = blockIdx.x;
    int t = threadIdx.x, lane = t & 31, wid = t >> 5;
    int qb = qt << 6;
    const float* hb = qkv + (size_t)b * SS * (3 * DD) + h * HDIM;

    uint32_t ksh = smem_u32(KsH), ksl = smem_u32(KsL);
    uint32_t vth = smem_u32(VtH), vtl = smem_u32(VtL);

    {
        int row = t >> 1;
        int ch0 = (t & 1) * 4;
        const float* src = hb + (size_t)(qb + row) * (3 * DD) + DD + ch0 * 8;
        #pragma unroll
        for (int c = 0; c < 4; c++) {
            float4 va = ((const float4*)src)[c * 2];
            float4 vb = ((const float4*)src)[c * 2 + 1];
            va.x *= 0.125f; va.y *= 0.125f; va.z *= 0.125f; va.w *= 0.125f;
            vb.x *= 0.125f; vb.y *= 0.125f; vb.z *= 0.125f; vb.w *= 0.125f;
            int off = row * 128 + (((ch0 + c) ^ (row & 7)) << 4);
            cvt_store(KsH + off,     KsL + off,     va);
            cvt_store(KsH + off + 8, KsL + off + 8, vb);
        }
    }
    __syncthreads();

    uint32_t qfh[4][4], qfl[4][4];
    #pragma unroll
    for (int kc = 0; kc < 4; kc++) {
        int row = wid * 16 + (lane & 15);
        int c = kc * 2 + (lane >> 4);
        uint32_t off = (uint32_t)(row * 128 + ((c ^ (row & 7)) << 4));
        ldsm4(qfh[kc], ksh + off);
        ldsm4(qfl[kc], ksl + off);
    }

    float o[8][4];
    #pragma unroll
    for (int i = 0; i < 8; i++)
        #pragma unroll
        for (int j = 0; j < 4; j++) o[i][j] = 0.f;
    float m0 = -1e30f, m1 = -1e30f, l0 = 0.f, l1 = 0.f;

    for (int kt = 0; kt <= qt; kt++) {
        __syncthreads();
        {
            int row = t >> 1;
            int ch0 = (t & 1) * 4;
            const float* src = hb + (size_t)((kt << 6) + row) * (3 * DD) + ch0 * 8;
            #pragma unroll
            for (int c = 0; c < 4; c++) {
                float4 va = ((const float4*)src)[c * 2];
                float4 vb = ((const float4*)src)[c * 2 + 1];
                int off = row * 128 + (((ch0 + c) ^ (row & 7)) << 4);
                cvt_store(KsH + off,     KsL + off,     va);
                cvt_store(KsH + off + 8, KsL + off + 8, vb);
            }
        }
        {
            int s0 = lane * 2;
            int db = wid * 16;
            const float* v0 = hb + (size_t)((kt << 6) + s0) * (3 * DD) + 2 * DD + db;
            const float* v1 = v0 + 3 * DD;
            #pragma unroll
            for (int dd = 0; dd < 16; dd += 4) {
                float4 x0 = *(const float4*)(v0 + dd);
                float4 x1 = *(const float4*)(v1 + dd);
                const float* a0 = (const float*)&x0;
                const float* a1 = (const float*)&x1;
                #pragma unroll
                for (int e = 0; e < 4; e++) {
                    int d = db + dd + e;
                    uint32_t hv, lv;
                    split2(a0[e], a1[e], hv, lv);
                    int off = d * 128 + (((s0 >> 3) ^ (d & 7)) << 4) + (s0 & 7) * 2;
                    *(uint32_t*)(VtH + off) = hv;
                    *(uint32_t*)(VtL + off) = lv;
                }
            }
        }
        __syncthreads();

        float s[8][4];
        #pragma unroll
        for (int i = 0; i < 8; i++)
            #pragma unroll
            for (int j = 0; j < 4; j++) s[i][j] = 0.f;

        #pragma unroll
        for (int kc = 0; kc < 4; kc++) {
            uint32_t kbh[8][2], kbl[8][2];
            #pragma unroll
            for (int np = 0; np < 4; np++) {
                int row = np * 16 + (lane & 15);
                int c = kc * 2 + (lane >> 4);
                uint32_t off = (uint32_t)(row * 128 + ((c ^ (row & 7)) << 4));
                uint32_t qq[4];
                ldsm4(qq, ksh + off);
                kbh[np*2][0] = qq[0]; kbh[np*2][1] = qq[2];
                kbh[np*2+1][0] = qq[1]; kbh[np*2+1][1] = qq[3];
                ldsm4(qq, ksl + off);
                kbl[np*2][0] = qq[0]; kbl[np*2][1] = qq[2];
                kbl[np*2+1][0] = qq[1]; kbl[np*2+1][1] = qq[3];
            }
            #pragma unroll
            for (int nt = 0; nt < 8; nt++) mma16816(s[nt], qfh[kc], kbh[nt]);
            #pragma unroll
            for (int nt = 0; nt < 8; nt++) mma16816(s[nt], qfh[kc], kbl[nt]);
            #pragma unroll
            for (int nt = 0; nt < 8; nt++) mma16816(s[nt], qfl[kc], kbh[nt]);
        }

        if (kt == qt) {
            int cb = (lane & 3) * 2;
            int r0 = wid * 16 + (lane >> 2), r1 = r0 + 8;
            #pragma unroll
            for (int nt = 0; nt < 8; nt++) {
                int c0 = nt * 8 + cb;
                if (c0     > r0) s[nt][0] = -1e30f;
                if (c0 + 1 > r0) s[nt][1] = -1e30f;
                if (c0     > r1) s[nt][2] = -1e30f;
                if (c0 + 1 > r1) s[nt][3] = -1e30f;
            }
        }

        float mx0 = -1e30f, mx1 = -1e30f;
        #pragma unroll
        for (int nt = 0; nt < 8; nt++) {
            mx0 = fmaxf(mx0, fmaxf(s[nt][0], s[nt][1]));
            mx1 = fmaxf(mx1, fmaxf(s[nt][2], s[nt][3]));
        }
        mx0 = fmaxf(mx0, __shfl_xor_sync(0xffffffffu, mx0, 1));
        mx0 = fmaxf(mx0, __shfl_xor_sync(0xffffffffu, mx0, 2));
        mx1 = fmaxf(mx1, __shfl_xor_sync(0xffffffffu, mx1, 1));
        mx1 = fmaxf(mx1, __shfl_xor_sync(0xffffffffu, mx1, 2));
        float mn0 = fmaxf(m0, mx0), mn1 = fmaxf(m1, mx1);
        float sc0 = __expf(m0 - mn0), sc1 = __expf(m1 - mn1);
        m0 = mn0; m1 = mn1;
        float su0 = 0.f, su1 = 0.f;
        #pragma unroll
        for (int nt = 0; nt < 8; nt++) {
            s[nt][0] = __expf(s[nt][0] - mn0); su0 += s[nt][0];
            s[nt][1] = __expf(s[nt][1] - mn0); su0 += s[nt][1];
            s[nt][2] = __expf(s[nt][2] - mn1); su1 += s[nt][2];
            s[nt][3] = __expf(s[nt][3] - mn1); su1 += s[nt][3];
        }
        su0 += __shfl_xor_sync(0xffffffffu, su0, 1);
        su0 += __shfl_xor_sync(0xffffffffu, su0, 2);
        su1 += __shfl_xor_sync(0xffffffffu, su1, 1);
        su1 += __shfl_xor_sync(0xffffffffu, su1, 2);
        l0 = l0 * sc0 + su0;
        l1 = l1 * sc1 + su1;
        #pragma unroll
        for (int nt = 0; nt < 8; nt++) {
            o[nt][0] *= sc0; o[nt][1] *= sc0;
            o[nt][2] *= sc1; o[nt][3] *= sc1;
        }

        #pragma unroll
        for (int kc = 0; kc < 4; kc++) {
            uint32_t pah[4], pal[4];
            split2(s[2*kc][0],   s[2*kc][1],   pah[0], pal[0]);
            split2(s[2*kc][2],   s[2*kc][3],   pah[1], pal[1]);
            split2(s[2*kc+1][0], s[2*kc+1][1], pah[2], pal[2]);
            split2(s[2*kc+1][2], s[2*kc+1][3], pah[3], pal[3]);
            uint32_t vbh[8][2], vbl[8][2];
            #pragma unroll
            for (int np = 0; np < 4; np++) {
                int row = np * 16 + (lane & 15);
                int c = kc * 2 + (lane >> 4);
                uint32_t off = (uint32_t)(row * 128 + ((c ^ (row & 7)) << 4));
                uint32_t qq[4];
                ldsm4(qq, vth + off);
                vbh[np*2][0] = qq[0]; vbh[np*2][1] = qq[2];
                vbh[np*2+1][0] = qq[1]; vbh[np*2+1][1] = qq[3];
                ldsm4(qq, vtl + off);
                vbl[np*2][0] = qq[0]; vbl[np*2][1] = qq[2];
                vbl[np*2+1][0] = qq[1]; vbl[np*2+1][1] = qq[3];
            }
            #pragma unroll
            for (int nt = 0; nt < 8; nt++) mma16816(o[nt], pah, vbh[nt]);
            #pragma unroll
            for (int nt = 0; nt < 8; nt++) mma16816(o[nt], pah, vbl[nt]);
            #pragma unroll
            for (int nt = 0; nt < 8; nt++) mma16816(o[nt], pal, vbh[nt]);
        }
    }

    // normalize + plain fp32 write
    float i0 = 1.0f / l0, i1 = 1.0f / l1;
    int r0 = qb + wid * 16 + (lane >> 2);
    size_t tok0 = (size_t)b * SS + r0;
    float* op0 = out + tok0 * DD + h * HDIM + (lane & 3) * 2;
    float* op1 = op0 + (size_t)8 * DD;     // row + 8
    #pragma unroll
    for (int nt = 0; nt < 8; nt++) {
        *(float2*)(op0 + nt * 8) = make_float2(o[nt][0] * i0, o[nt][1] * i0);
        *(float2*)(op1 + nt * 8) = make_float2(o[nt][2] * i1, o[nt][3] * i1);
    }
}

// ---------------------------------------------------------------------------
// Orchestration (graph-capturable: kernel launches only)
// ---------------------------------------------------------------------------
extern "C" void kernel_launch(void* const* d_in, const int* in_sizes, int n_in,
                              void* d_out, int out_size) {
    const int*   idx    = (const int*)  d_in[0];
    const float* wte    = (const float*)d_in[1];
    const float* wpe    = (const float*)d_in[2];
    const float* ln1w   = (const float*)d_in[3];
    const float* ln1b   = (const float*)d_in[4];
    const float* qkvw   = (const float*)d_in[5];
    const float* qkvb   = (const float*)d_in[6];
    const float* projw  = (const float*)d_in[7];
    const float* projb  = (const float*)d_in[8];
    const float* ln2w   = (const float*)d_in[9];
    const float* ln2b   = (const float*)d_in[10];
    const float* fcw    = (const float*)d_in[11];
    const float* fcb    = (const float*)d_in[12];
    const float* cprojw = (const float*)d_in[13];
    const float* cprojb = (const float*)d_in[14];
    const float* lnfw   = (const float*)d_in[15];
    const float* lnfb   = (const float*)d_in[16];
    const float* headw  = (const float*)d_in[17];
    float* out = (float*)d_out;

    float *px, *pq, *pat, *pfc, *psa, *psw;
    char *pxh, *pxl, *pwh, *pwl;
    cudaGetSymbolAddress((void**)&px,  g_x);
    cudaGetSymbolAddress((void**)&pq,  g_qkv);
    cudaGetSymbolAddress((void**)&pat, g_attn);
    cudaGetSymbolAddress((void**)&pfc, g_fc);
    cudaGetSymbolAddress((void**)&pxh, g_xah);
    cudaGetSymbolAddress((void**)&pxl, g_xal);
    cudaGetSymbolAddress((void**)&pwh, g_wh);
    cudaGetSymbolAddress((void**)&pwl, g_wl);
    cudaGetSymbolAddress((void**)&psa, g_sa);
    cudaGetSymbolAddress((void**)&psw, g_sw);

    cudaFuncSetAttribute(gemm_i8<0>, cudaFuncAttributeMaxDynamicSharedMemorySize, GEMM_SMEM);
    cudaFuncSetAttribute(gemm_i8<1>, cudaFuncAttributeMaxDynamicSharedMemorySize, GEMM_SMEM);
    cudaFuncSetAttribute(gemm_i8<2>, cudaFuncAttributeMaxDynamicSharedMemorySize, GEMM_SMEM);
    cudaFuncSetAttribute(gemm_i8<3>, cudaFuncAttributeMaxDynamicSharedMemorySize, GEMM_SMEM);

    embed_k<<<MTOK, 256>>>(idx, wte, wpe, px);

    for (int l = 0; l < LL; l++) {
        // --- qkv ---
        ln_k<<<MTOK, 256>>>(px, ln1w + (size_t)l * DD, ln1b + (size_t)l * DD, pxh, pxl, psa);
        cvt_a<<<3 * DD, 256>>>(qkvw + (size_t)l * 3 * DD * DD, pwh, pwl, psw, DD);
        gemm_i8<0><<<dim3(3 * DD / 128, MTOK / 128), 256, GEMM_SMEM>>>(
            pxh, pxl, pwh, pwl, psa, psw, qkvb + (size_t)l * 3 * DD, pq,
            MTOK, 3 * DD, DD);
        // --- attention ---
        attn_k<<<dim3(SS / 64, HH, BB), 128>>>(pq, pat);
        // --- proj (+residual) ---
        cvt_a<<<MTOK, 256>>>(pat, pxh, pxl, psa, DD);
        cvt_a<<<DD, 256>>>(projw + (size_t)l * DD * DD, pwh, pwl, psw, DD);
        gemm_i8<2><<<dim3(DD / 128, MTOK / 128), 256, GEMM_SMEM>>>(
            pxh, pxl, pwh, pwl, psa, psw, projb + (size_t)l * DD, px,
            MTOK, DD, DD);
        // --- fc + gelu (fp32 out) ---
        ln_k<<<MTOK, 256>>>(px, ln2w + (size_t)l * DD, ln2b + (size_t)l * DD, pxh, pxl, psa);
        cvt_a<<<4 * DD, 256>>>(fcw + (size_t)l * 4 * DD * DD, pwh, pwl, psw, DD);
        gemm_i8<1><<<dim3(4 * DD / 128, MTOK / 128), 256, GEMM_SMEM>>>(
            pxh, pxl, pwh, pwl, psa, psw, fcb + (size_t)l * 4 * DD, pfc,
            MTOK, 4 * DD, DD);
        // --- cproj (+residual) ---
        cvt_a<<<MTOK, 256>>>(pfc, pxh, pxl, psa, 4 * DD);
        cvt_a<<<DD, 256>>>(cprojw + (size_t)l * DD * 4 * DD, pwh, pwl, psw, 4 * DD);
        gemm_i8<2><<<dim3(DD / 128, MTOK / 128), 256, GEMM_SMEM>>>(
            pxh, pxl, pwh, pwl, psa, psw, cprojb + (size_t)l * DD, px,
            MTOK, DD, 4 * DD);
    }

    ln_k<<<MTOK, 256>>>(px, lnfw, lnfb, pxh, pxl, psa);
    cvt_a<<<VV, 256>>>(headw, pwh, pwl, psw, DD);
    gemm_i8<3><<<dim3(VV / 128, MTOK / 128), 256, GEMM_SMEM>>>(
        pxh, pxl, pwh, pwl, psa, psw, nullptr, out, MTOK, VV, DD);
}

// round 17
// speedup vs baseline: 2.6419x; 2.6419x over previous
#include <cuda_runtime.h>
#include <cuda_fp16.h>
#include <cstdint>
#include <cstddef>

// Problem constants
#define BB 4
#define SS 2048
#define DD 1024
#define HH 16
#define LL 8
#define VV 8192
#define HDIM 64
#define MTOK (BB*SS)   // 8192 tokens

typedef unsigned long long ull;

// ---------------------------------------------------------------------------
// Static device scratch (no allocations allowed)
// ---------------------------------------------------------------------------
__device__ float    g_x  [(size_t)MTOK * DD];           // residual fp32
__device__ float    g_qkv[(size_t)MTOK * 3 * DD];       // qkv fp32
__device__ __align__(16) uint32_t g_ah[(size_t)MTOK * DD / 2];       // act hi fp16
__device__ __align__(16) uint32_t g_al[(size_t)MTOK * DD / 2];       // act lo fp16
__device__ __align__(16) uint32_t g_fh[(size_t)MTOK * 4 * DD / 2];   // fc hi
__device__ __align__(16) uint32_t g_fl[(size_t)MTOK * 4 * DD / 2];   // fc lo
__device__ __align__(16) uint32_t g_bh[(size_t)VV * DD / 2];         // weight hi fp16

// ---------------------------------------------------------------------------
// Helpers
// ---------------------------------------------------------------------------
__device__ __forceinline__ float gelu_f(float x) {
    float z = 0.7978845608028654f * (x + 0.044715f * x * x * x);
    float e = __expf(2.0f * z);
    float th = 1.0f - 2.0f / (e + 1.0f);
    return 0.5f * x * (1.0f + th);
}

// bf16x2 pack: {hi(y) | lo(x)}  (attention-internal only)
__device__ __forceinline__ uint32_t bf2(float lo, float hi) {
    uint32_t r; asm("cvt.rn.bf16x2.f32 %0, %1, %2;" : "=r"(r) : "f"(hi), "f"(lo)); return r;
}
// bf16 split (attention-internal)
__device__ __forceinline__ void split2(float x, float y, uint32_t& hi, uint32_t& lo) {
    hi = bf2(x, y);
    float rx = x - __uint_as_float(hi << 16);
    float ry = y - __uint_as_float(hi & 0xffff0000u);
    lo = bf2(rx, ry);
}

// fp16x2 pack (x low, y high) + residual split
__device__ __forceinline__ uint32_t h2pack(float x, float y) {
    __half2 h = __floats2half2_rn(x, y);
    return *(uint32_t*)&h;
}
__device__ __forceinline__ void split2h(float x, float y, uint32_t& hi, uint32_t& lo) {
    __half2 h = __floats2half2_rn(x, y);
    hi = *(uint32_t*)&h;
    float2 f = __half22float2(h);
    __half2 l = __floats2half2_rn(x - f.x, y - f.y);
    lo = *(uint32_t*)&l;
}

__device__ __forceinline__ uint32_t smem_u32(const void* p) {
    uint32_t a;
    asm("{ .reg .u64 t; cvta.to.shared.u64 t, %1; cvt.u32.u64 %0, t; }" : "=r"(a) : "l"(p));
    return a;
}

// ---------------------------------------------------------------------------
// mma.sync / ldmatrix / cp.async (sm_80-compatible path)
// ---------------------------------------------------------------------------
__device__ __forceinline__ void ldsm4(uint32_t* r, uint32_t addr) {
    asm volatile("ldmatrix.sync.aligned.m8n8.x4.shared.b16 {%0,%1,%2,%3}, [%4];"
        : "=r"(r[0]), "=r"(r[1]), "=r"(r[2]), "=r"(r[3]) : "r"(addr));
}
// bf16 variant (attention)
__device__ __forceinline__ void mma16816(float* c, const uint32_t* a, const uint32_t* b) {
    asm volatile(
        "mma.sync.aligned.m16n8k16.row.col.f32.bf16.bf16.f32 "
        "{%0,%1,%2,%3}, {%4,%5,%6,%7}, {%8,%9}, {%0,%1,%2,%3};"
        : "+f"(c[0]), "+f"(c[1]), "+f"(c[2]), "+f"(c[3])
        : "r"(a[0]), "r"(a[1]), "r"(a[2]), "r"(a[3]), "r"(b[0]), "r"(b[1]));
}
// fp16, fp32 accumulate (GEMM hi term)
__device__ __forceinline__ void mma16816h(float* c, const uint32_t* a, const uint32_t* b) {
    asm volatile(
        "mma.sync.aligned.m16n8k16.row.col.f32.f16.f16.f32 "
        "{%0,%1,%2,%3}, {%4,%5,%6,%7}, {%8,%9}, {%0,%1,%2,%3};"
        : "+f"(c[0]), "+f"(c[1]), "+f"(c[2]), "+f"(c[3])
        : "r"(a[0]), "r"(a[1]), "r"(a[2]), "r"(a[3]), "r"(b[0]), "r"(b[1]));
}
// fp16, fp16 accumulate (GEMM lo term — speculative 2x issue rate)
__device__ __forceinline__ void mma16816hh(uint32_t* c, const uint32_t* a, const uint32_t* b) {
    asm volatile(
        "mma.sync.aligned.m16n8k16.row.col.f16.f16.f16.f16 "
        "{%0,%1}, {%2,%3,%4,%5}, {%6,%7}, {%0,%1};"
        : "+r"(c[0]), "+r"(c[1])
        : "r"(a[0]), "r"(a[1]), "r"(a[2]), "r"(a[3]), "r"(b[0]), "r"(b[1]));
}
__device__ __forceinline__ void cpa16(uint32_t dst, const void* src) {
    size_t g = __cvta_generic_to_global(src);
    asm volatile("cp.async.cg.shared.global [%0], [%1], 16;" :: "r"(dst), "l"(g) : "memory");
}
#define CPA_COMMIT() asm volatile("cp.async.commit_group;" ::: "memory")
#define CPA_WAIT1()  asm volatile("cp.async.wait_group 1;"  ::: "memory")

// fp32x4 -> bf16 hi/lo (attention-internal tiles)
__device__ __forceinline__ void cvt_store(void* hi, void* lo, float4 v) {
    uint32_t h0 = bf2(v.x, v.y);
    uint32_t h1 = bf2(v.z, v.w);
    float bx = __uint_as_float(h0 << 16);
    float by = __uint_as_float(h0 & 0xffff0000u);
    float bz = __uint_as_float(h1 << 16);
    float bw = __uint_as_float(h1 & 0xffff0000u);
    uint32_t l0 = bf2(v.x - bx, v.y - by);
    uint32_t l1 = bf2(v.z - bz, v.w - bw);
    *(ull*)hi = ((ull)h1 << 32) | h0;
    *(ull*)lo = ((ull)l1 << 32) | l0;
}

// fp32x4 -> fp16 hi (8B) + fp16 lo residual (8B)
__device__ __forceinline__ void cvt_storeh(void* hi, void* lo, float4 v) {
    uint32_t h0, l0, h1, l1;
    split2h(v.x, v.y, h0, l0);
    split2h(v.z, v.w, h1, l1);
    *(ull*)hi = ((ull)h1 << 32) | h0;
    *(ull*)lo = ((ull)l1 << 32) | l0;
}

// ---------------------------------------------------------------------------
// Weight conversion: fp32 -> fp16 hi only (B operand is single-plane)
// ---------------------------------------------------------------------------
__global__ void cvt_w(const float* __restrict__ W, uint32_t* __restrict__ hi, int n4) {
    int i = blockIdx.x * 256 + threadIdx.x;
    if (i >= n4) return;
    float4 v = ((const float4*)W)[i];
    uint32_t h0 = h2pack(v.x, v.y);
    uint32_t h1 = h2pack(v.z, v.w);
    ((ull*)hi)[i] = ((ull)h1 << 32) | h0;
}

// ---------------------------------------------------------------------------
// Embedding
// ---------------------------------------------------------------------------
__global__ void embed_k(const int* __restrict__ idx, const float* __restrict__ wte,
                        const float* __restrict__ wpe, float* __restrict__ x) {
    int row = blockIdx.x;
    int s   = row & (SS - 1);
    int t   = threadIdx.x;
    int tok = idx[row];
    float4 a = ((const float4*)(wte + (size_t)tok * DD))[t];
    float4 p = ((const float4*)(wpe + (size_t)s * DD))[t];
    ((float4*)(x + (size_t)row * DD))[t] =
        make_float4(a.x + p.x, a.y + p.y, a.z + p.z, a.w + p.w);
}

// ---------------------------------------------------------------------------
// LayerNorm -> split fp16 output (GEMM A operand)
// ---------------------------------------------------------------------------
__global__ void ln_k(const float* __restrict__ x, const float* __restrict__ w,
                     const float* __restrict__ b, uint32_t* __restrict__ ohi,
                     uint32_t* __restrict__ olo) {
    int row = blockIdx.x;
    int t   = threadIdx.x;
    float4 v = ((const float4*)(x + (size_t)row * DD))[t];
    float s = v.x + v.y + v.z + v.w;
    float q = v.x * v.x + v.y * v.y + v.z * v.z + v.w * v.w;
    #pragma unroll
    for (int off = 16; off; off >>= 1) {
        s += __shfl_xor_sync(0xffffffffu, s, off);
        q += __shfl_xor_sync(0xffffffffu, q, off);
    }
    __shared__ float ss[8], sq[8];
    __shared__ float smu, srs;
    int wid = t >> 5;
    if ((t & 31) == 0) { ss[wid] = s; sq[wid] = q; }
    __syncthreads();
    if (t == 0) {
        float S = 0.f, Q = 0.f;
        #pragma unroll
        for (int i = 0; i < 8; i++) { S += ss[i]; Q += sq[i]; }
        float mu  = S * (1.0f / DD);
        float var = Q * (1.0f / DD) - mu * mu;
        smu = mu;
        srs = rsqrtf(var + 1e-5f);
    }
    __syncthreads();
    float mu = smu, r = srs;
    float4 wv = ((const float4*)w)[t];
    float4 bv = ((const float4*)b)[t];
    float4 out;
    out.x = (v.x - mu) * r * wv.x + bv.x;
    out.y = (v.y - mu) * r * wv.y + bv.y;
    out.z = (v.z - mu) * r * wv.z + bv.z;
    out.w = (v.w - mu) * r * wv.w + bv.w;
    size_t i = (size_t)row * (DD / 4) + t;
    cvt_storeh((ull*)ohi + i, (ull*)olo + i, out);
}

// ---------------------------------------------------------------------------
// Tensor-core NT GEMM, fp16 two-term: C = (Ah+Al) * Bh^T.
// Hi term: fp32 accumulate. Lo term: fp16 accumulate (magnitude ~2^-11 of hi;
// fp16 precision on it contributes ~2^-22 relative — negligible; probes the
// legacy pipe's fp16-acc double-rate).
// CTA 128x128, K-step 32, 3-stage cp.async (24KB/stage), 2 CTAs/SM.
// EPI: 0 = fp32 +bias, 1 = gelu(+bias) -> fp16 hi/lo, 2 = fp32 += acc+bias,
//      3 = fp32 plain
// ---------------------------------------------------------------------------
#define STAGE 24576
#define PL_AH 0
#define PL_AL 8192
#define PL_BH 16384
#define GEMM_SMEM (3*STAGE)

template<int EPI>
__global__ void __launch_bounds__(256, 2)
gemm_bf(const char* __restrict__ Ah, const char* __restrict__ Al,
        const char* __restrict__ Bh,
        const float* __restrict__ bias, float* __restrict__ C,
        uint32_t* __restrict__ Chi, uint32_t* __restrict__ Clo,
        int M, int N, int K)
{
    extern __shared__ __align__(16) char sm[];
    int tid  = threadIdx.x;
    int lane = tid & 31;
    int w    = tid >> 5;
    int wm   = w & 1;
    int wn   = w >> 1;
    int bn = blockIdx.x << 7, bm = blockIdx.y << 7;
    uint32_t smb = smem_u32(sm);

    float    acc [4][4][4];
    uint32_t accl[4][4][2];
    #pragma unroll
    for (int i = 0; i < 4; i++)
        #pragma unroll
        for (int j = 0; j < 4; j++) {
            #pragma unroll
            for (int r = 0; r < 4; r++) acc[i][j][r] = 0.f;
            accl[i][j][0] = 0u; accl[i][j][1] = 0u;
        }

    int nk = K >> 5;
    int lr = tid >> 1;
    int q0 = (tid & 1) << 1;
    size_t arow = (size_t)(bm + lr) * K;
    size_t brow = (size_t)(bn + lr) * K;
    int sw = (lr >> 1) & 3;

    auto fill = [&](int slot, int ks) {
        int kc = ks << 5;
        uint32_t sb = smb + slot * STAGE + lr * 64;
        #pragma unroll
        for (int c = 0; c < 2; c++) {
            int q = q0 + c;
            uint32_t d = sb + ((q ^ sw) << 4);
            size_t ao = (arow + kc + q * 8) * 2;
            size_t bo = (brow + kc + q * 8) * 2;
            cpa16(d + PL_AH, Ah + ao);
            cpa16(d + PL_AL, Al + ao);
            cpa16(d + PL_BH, Bh + bo);
        }
    };
    fill(0, 0); CPA_COMMIT();
    fill(1, 1); CPA_COMMIT();

    for (int t = 0; t < nk; t++) {
        CPA_WAIT1();
        __syncthreads();
        if (t + 2 < nk) fill((t + 2) % 3, t + 2);
        CPA_COMMIT();

        uint32_t base = smb + (t % 3) * STAGE;
        #pragma unroll
        for (int kh = 0; kh < 2; kh++) {
            int cch = kh * 2 + (lane >> 4);
            uint32_t ahf[4][4], alf[4][4];
            #pragma unroll
            for (int mi = 0; mi < 4; mi++) {
                int row = wm * 64 + mi * 16 + (lane & 15);
                uint32_t ad = base + row * 64 + ((cch ^ ((row >> 1) & 3)) << 4);
                ldsm4(ahf[mi], ad + PL_AH);
                ldsm4(alf[mi], ad + PL_AL);
            }
            uint32_t bhq[2][4];
            #pragma unroll
            for (int np = 0; np < 2; np++) {
                int row = wn * 32 + np * 16 + (lane & 15);
                uint32_t bd = base + row * 64 + ((cch ^ ((row >> 1) & 3)) << 4);
                ldsm4(bhq[np], bd + PL_BH);
            }
            uint32_t bhf[4][2];
            #pragma unroll
            for (int np = 0; np < 2; np++)
                #pragma unroll
                for (int sdx = 0; sdx < 2; sdx++) {
                    bhf[np * 2 + sdx][0] = bhq[np][sdx];
                    bhf[np * 2 + sdx][1] = bhq[np][sdx + 2];
                }
            #pragma unroll
            for (int mi = 0; mi < 4; mi++)
                #pragma unroll
                for (int ni = 0; ni < 4; ni++)
                    mma16816h(acc[mi][ni], ahf[mi], bhf[ni]);
            #pragma unroll
            for (int mi = 0; mi < 4; mi++)
                #pragma unroll
                for (int ni = 0; ni < 4; ni++)
                    mma16816hh(accl[mi][ni], alf[mi], bhf[ni]);
        }
    }

    int rbase = bm + wm * 64 + (lane >> 2);
    int cbase = bn + wn * 32 + ((lane & 3) << 1);
    #pragma unroll
    for (int mi = 0; mi < 4; mi++) {
        #pragma unroll
        for (int ni = 0; ni < 4; ni++) {
            float* cc = acc[mi][ni];
            int col  = cbase + ni * 8;
            int row0 = rbase + mi * 16;
            float b0 = 0.f, b1 = 0.f;
            if (EPI != 3) { b0 = bias[col]; b1 = bias[col + 1]; }
            #pragma unroll
            for (int half = 0; half < 2; half++) {
                int row = row0 + half * 8;
                float2 lo = __half22float2(*(__half2*)&accl[mi][ni][half]);
                float vx = cc[half * 2]     + lo.x + b0;
                float vy = cc[half * 2 + 1] + lo.y + b1;
                if (EPI == 1) {
                    vx = gelu_f(vx); vy = gelu_f(vy);
                    uint32_t hv, lv;
                    split2h(vx, vy, hv, lv);
                    size_t idx = ((size_t)row * N + col) >> 1;
                    Chi[idx] = hv;
                    Clo[idx] = lv;
                } else {
                    float* cp = C + (size_t)row * N + col;
                    if (EPI == 2) {
                        float2 o = *(const float2*)cp;
                        vx += o.x; vy += o.y;
                    }
                    *(float2*)cp = make_float2(vx, vy);
                }
            }
        }
    }
}

// ---------------------------------------------------------------------------
// Tensor-core flash attention (causal) — internal bf16x3 (proven R12 body);
// output written as split fp16 (proj GEMM A operand).
// ---------------------------------------------------------------------------
__global__ __launch_bounds__(128) void attn_k(const float* __restrict__ qkv,
                                              uint32_t* __restrict__ ohi,
                                              uint32_t* __restrict__ olo) {
    __shared__ __align__(16) char KsH[8192];
    __shared__ __align__(16) char KsL[8192];
    __shared__ __align__(16) char VtH[8192];
    __shared__ __align__(16) char VtL[8192];

    int b = blockIdx.z, h = blockIdx.y, qt = blockIdx.x;
    int t = threadIdx.x, lane = t & 31, wid = t >> 5;
    int qb = qt << 6;
    const float* hb = qkv + (size_t)b * SS * (3 * DD) + h * HDIM;

    uint32_t ksh = smem_u32(KsH), ksl = smem_u32(KsL);
    uint32_t vth = smem_u32(VtH), vtl = smem_u32(VtL);

    {
        int row = t >> 1;
        int ch0 = (t & 1) * 4;
        const float* src = hb + (size_t)(qb + row) * (3 * DD) + DD + ch0 * 8;
        #pragma unroll
        for (int c = 0; c < 4; c++) {
            float4 va = ((const float4*)src)[c * 2];
            float4 vb = ((const float4*)src)[c * 2 + 1];
            va.x *= 0.125f; va.y *= 0.125f; va.z *= 0.125f; va.w *= 0.125f;
            vb.x *= 0.125f; vb.y *= 0.125f; vb.z *= 0.125f; vb.w *= 0.125f;
            int off = row * 128 + (((ch0 + c) ^ (row & 7)) << 4);
            cvt_store(KsH + off,     KsL + off,     va);
            cvt_store(KsH + off + 8, KsL + off + 8, vb);
        }
    }
    __syncthreads();

    uint32_t qfh[4][4], qfl[4][4];
    #pragma unroll
    for (int kc = 0; kc < 4; kc++) {
        int row = wid * 16 + (lane & 15);
        int c = kc * 2 + (lane >> 4);
        uint32_t off = (uint32_t)(row * 128 + ((c ^ (row & 7)) << 4));
        ldsm4(qfh[kc], ksh + off);
        ldsm4(qfl[kc], ksl + off);
    }

    float o[8][4];
    #pragma unroll
    for (int i = 0; i < 8; i++)
        #pragma unroll
        for (int j = 0; j < 4; j++) o[i][j] = 0.f;
    float m0 = -1e30f, m1 = -1e30f, l0 = 0.f, l1 = 0.f;

    for (int kt = 0; kt <= qt; kt++) {
        __syncthreads();
        {
            int row = t >> 1;
            int ch0 = (t & 1) * 4;
            const float* src = hb + (size_t)((kt << 6) + row) * (3 * DD) + ch0 * 8;
            #pragma unroll
            for (int c = 0; c < 4; c++) {
                float4 va = ((const float4*)src)[c * 2];
                float4 vb = ((const float4*)src)[c * 2 + 1];
                int off = row * 128 + (((ch0 + c) ^ (row & 7)) << 4);
                cvt_store(KsH + off,     KsL + off,     va);
                cvt_store(KsH + off + 8, KsL + off + 8, vb);
            }
        }
        {
            int s0 = lane * 2;
            int db = wid * 16;
            const float* v0 = hb + (size_t)((kt << 6) + s0) * (3 * DD) + 2 * DD + db;
            const float* v1 = v0 + 3 * DD;
            #pragma unroll
            for (int dd = 0; dd < 16; dd += 4) {
                float4 x0 = *(const float4*)(v0 + dd);
                float4 x1 = *(const float4*)(v1 + dd);
                const float* a0 = (const float*)&x0;
                const float* a1 = (const float*)&x1;
                #pragma unroll
                for (int e = 0; e < 4; e++) {
                    int d = db + dd + e;
                    uint32_t hv, lv;
                    split2(a0[e], a1[e], hv, lv);
                    int off = d * 128 + (((s0 >> 3) ^ (d & 7)) << 4) + (s0 & 7) * 2;
                    *(uint32_t*)(VtH + off) = hv;
                    *(uint32_t*)(VtL + off) = lv;
                }
            }
        }
        __syncthreads();

        float s[8][4];
        #pragma unroll
        for (int i = 0; i < 8; i++)
            #pragma unroll
            for (int j = 0; j < 4; j++) s[i][j] = 0.f;

        #pragma unroll
        for (int kc = 0; kc < 4; kc++) {
            uint32_t kbh[8][2], kbl[8][2];
            #pragma unroll
            for (int np = 0; np < 4; np++) {
                int row = np * 16 + (lane & 15);
                int c = kc * 2 + (lane >> 4);
                uint32_t off = (uint32_t)(row * 128 + ((c ^ (row & 7)) << 4));
                uint32_t qq[4];
                ldsm4(qq, ksh + off);
                kbh[np*2][0] = qq[0]; kbh[np*2][1] = qq[2];
                kbh[np*2+1][0] = qq[1]; kbh[np*2+1][1] = qq[3];
                ldsm4(qq, ksl + off);
                kbl[np*2][0] = qq[0]; kbl[np*2][1] = qq[2];
                kbl[np*2+1][0] = qq[1]; kbl[np*2+1][1] = qq[3];
            }
            #pragma unroll
            for (int nt = 0; nt < 8; nt++) mma16816(s[nt], qfh[kc], kbh[nt]);
            #pragma unroll
            for (int nt = 0; nt < 8; nt++) mma16816(s[nt], qfh[kc], kbl[nt]);
            #pragma unroll
            for (int nt = 0; nt < 8; nt++) mma16816(s[nt], qfl[kc], kbh[nt]);
        }

        if (kt == qt) {
            int cb = (lane & 3) * 2;
            int r0 = wid * 16 + (lane >> 2), r1 = r0 + 8;
            #pragma unroll
            for (int nt = 0; nt < 8; nt++) {
                int c0 = nt * 8 + cb;
                if (c0     > r0) s[nt][0] = -1e30f;
                if (c0 + 1 > r0) s[nt][1] = -1e30f;
                if (c0     > r1) s[nt][2] = -1e30f;
                if (c0 + 1 > r1) s[nt][3] = -1e30f;
            }
        }

        float mx0 = -1e30f, mx1 = -1e30f;
        #pragma unroll
        for (int nt = 0; nt < 8; nt++) {
            mx0 = fmaxf(mx0, fmaxf(s[nt][0], s[nt][1]));
            mx1 = fmaxf(mx1, fmaxf(s[nt][2], s[nt][3]));
        }
        mx0 = fmaxf(mx0, __shfl_xor_sync(0xffffffffu, mx0, 1));
        mx0 = fmaxf(mx0, __shfl_xor_sync(0xffffffffu, mx0, 2));
        mx1 = fmaxf(mx1, __shfl_xor_sync(0xffffffffu, mx1, 1));
        mx1 = fmaxf(mx1, __shfl_xor_sync(0xffffffffu, mx1, 2));
        float mn0 = fmaxf(m0, mx0), mn1 = fmaxf(m1, mx1);
        float sc0 = __expf(m0 - mn0), sc1 = __expf(m1 - mn1);
        m0 = mn0; m1 = mn1;
        float su0 = 0.f, su1 = 0.f;
        #pragma unroll
        for (int nt = 0; nt < 8; nt++) {
            s[nt][0] = __expf(s[nt][0] - mn0); su0 += s[nt][0];
            s[nt][1] = __expf(s[nt][1] - mn0); su0 += s[nt][1];
            s[nt][2] = __expf(s[nt][2] - mn1); su1 += s[nt][2];
            s[nt][3] = __expf(s[nt][3] - mn1); su1 += s[nt][3];
        }
        su0 += __shfl_xor_sync(0xffffffffu, su0, 1);
        su0 += __shfl_xor_sync(0xffffffffu, su0, 2);
        su1 += __shfl_xor_sync(0xffffffffu, su1, 1);
        su1 += __shfl_xor_sync(0xffffffffu, su1, 2);
        l0 = l0 * sc0 + su0;
        l1 = l1 * sc1 + su1;
        #pragma unroll
        for (int nt = 0; nt < 8; nt++) {
            o[nt][0] *= sc0; o[nt][1] *= sc0;
            o[nt][2] *= sc1; o[nt][3] *= sc1;
        }

        #pragma unroll
        for (int kc = 0; kc < 4; kc++) {
            uint32_t pah[4], pal[4];
            split2(s[2*kc][0],   s[2*kc][1],   pah[0], pal[0]);
            split2(s[2*kc][2],   s[2*kc][3],   pah[1], pal[1]);
            split2(s[2*kc+1][0], s[2*kc+1][1], pah[2], pal[2]);
            split2(s[2*kc+1][2], s[2*kc+1][3], pah[3], pal[3]);
            uint32_t vbh[8][2], vbl[8][2];
            #pragma unroll
            for (int np = 0; np < 4; np++) {
                int row = np * 16 + (lane & 15);
                int c = kc * 2 + (lane >> 4);
                uint32_t off = (uint32_t)(row * 128 + ((c ^ (row & 7)) << 4));
                uint32_t qq[4];
                ldsm4(qq, vth + off);
                vbh[np*2][0] = qq[0]; vbh[np*2][1] = qq[2];
                vbh[np*2+1][0] = qq[1]; vbh[np*2+1][1] = qq[3];
                ldsm4(qq, vtl + off);
                vbl[np*2][0] = qq[0]; vbl[np*2][1] = qq[2];
                vbl[np*2+1][0] = qq[1]; vbl[np*2+1][1] = qq[3];
            }
            #pragma unroll
            for (int nt = 0; nt < 8; nt++) mma16816(o[nt], pah, vbh[nt]);
            #pragma unroll
            for (int nt = 0; nt < 8; nt++) mma16816(o[nt], pah, vbl[nt]);
            #pragma unroll
            for (int nt = 0; nt < 8; nt++) mma16816(o[nt], pal, vbh[nt]);
        }
    }

    // ---- normalize + write split fp16 (proj GEMM A operand) ----
    float i0 = 1.0f / l0, i1 = 1.0f / l1;
    int r0 = qb + wid * 16 + (lane >> 2);
    size_t tok0 = (size_t)b * SS + r0;
    size_t base0 = (tok0 * DD + h * HDIM + (lane & 3) * 2) >> 1;
    size_t base1 = base0 + (size_t)4 * DD;   // row + 8
    #pragma unroll
    for (int nt = 0; nt < 8; nt++) {
        uint32_t hv, lv;
        split2h(o[nt][0] * i0, o[nt][1] * i0, hv, lv);
        ohi[base0 + nt * 4] = hv;
        olo[base0 + nt * 4] = lv;
        split2h(o[nt][2] * i1, o[nt][3] * i1, hv, lv);
        ohi[base1 + nt * 4] = hv;
        olo[base1 + nt * 4] = lv;
    }
}

// ---------------------------------------------------------------------------
// Orchestration (graph-capturable: kernel launches only)
// ---------------------------------------------------------------------------
extern "C" void kernel_launch(void* const* d_in, const int* in_sizes, int n_in,
                              void* d_out, int out_size) {
    const int*   idx    = (const int*)  d_in[0];
    const float* wte    = (const float*)d_in[1];
    const float* wpe    = (const float*)d_in[2];
    const float* ln1w   = (const float*)d_in[3];
    const float* ln1b   = (const float*)d_in[4];
    const float* qkvw   = (const float*)d_in[5];
    const float* qkvb   = (const float*)d_in[6];
    const float* projw  = (const float*)d_in[7];
    const float* projb  = (const float*)d_in[8];
    const float* ln2w   = (const float*)d_in[9];
    const float* ln2b   = (const float*)d_in[10];
    const float* fcw    = (const float*)d_in[11];
    const float* fcb    = (const float*)d_in[12];
    const float* cprojw = (const float*)d_in[13];
    const float* cprojb = (const float*)d_in[14];
    const float* lnfw   = (const float*)d_in[15];
    const float* lnfb   = (const float*)d_in[16];
    const float* headw  = (const float*)d_in[17];
    float* out = (float*)d_out;

    float *px, *pq;
    uint32_t *pah, *pal, *pfh, *pfl, *pbh;
    cudaGetSymbolAddress((void**)&px,  g_x);
    cudaGetSymbolAddress((void**)&pq,  g_qkv);
    cudaGetSymbolAddress((void**)&pah, g_ah);
    cudaGetSymbolAddress((void**)&pal, g_al);
    cudaGetSymbolAddress((void**)&pfh, g_fh);
    cudaGetSymbolAddress((void**)&pfl, g_fl);
    cudaGetSymbolAddress((void**)&pbh, g_bh);

    cudaFuncSetAttribute(gemm_bf<0>, cudaFuncAttributeMaxDynamicSharedMemorySize, GEMM_SMEM);
    cudaFuncSetAttribute(gemm_bf<1>, cudaFuncAttributeMaxDynamicSharedMemorySize, GEMM_SMEM);
    cudaFuncSetAttribute(gemm_bf<2>, cudaFuncAttributeMaxDynamicSharedMemorySize, GEMM_SMEM);
    cudaFuncSetAttribute(gemm_bf<3>, cudaFuncAttributeMaxDynamicSharedMemorySize, GEMM_SMEM);

    embed_k<<<MTOK, 256>>>(idx, wte, wpe, px);

    for (int l = 0; l < LL; l++) {
        // --- qkv ---
        ln_k<<<MTOK, 256>>>(px, ln1w + (size_t)l * DD, ln1b + (size_t)l * DD, pah, pal);
        cvt_w<<<3 * DD * DD / 1024, 256>>>(qkvw + (size_t)l * 3 * DD * DD, pbh, 3 * DD * DD / 4);
        gemm_bf<0><<<dim3(3 * DD / 128, MTOK / 128), 256, GEMM_SMEM>>>(
            (const char*)pah, (const char*)pal, (const char*)pbh,
            qkvb + (size_t)l * 3 * DD, pq, nullptr, nullptr, MTOK, 3 * DD, DD);
        // --- attention (tensor-core flash) ---
        attn_k<<<dim3(SS / 64, HH, BB), 128>>>(pq, pah, pal);
        // --- proj (+residual) ---
        cvt_w<<<DD * DD / 1024, 256>>>(projw + (size_t)l * DD * DD, pbh, DD * DD / 4);
        gemm_bf<2><<<dim3(DD / 128, MTOK / 128), 256, GEMM_SMEM>>>(
            (const char*)pah, (const char*)pal, (const char*)pbh,
            projb + (size_t)l * DD, px, nullptr, nullptr, MTOK, DD, DD);
        // --- fc + gelu ---
        ln_k<<<MTOK, 256>>>(px, ln2w + (size_t)l * DD, ln2b + (size_t)l * DD, pah, pal);
        cvt_w<<<4 * DD * DD / 1024, 256>>>(fcw + (size_t)l * 4 * DD * DD, pbh, 4 * DD * DD / 4);
        gemm_bf<1><<<dim3(4 * DD / 128, MTOK / 128), 256, GEMM_SMEM>>>(
            (const char*)pah, (const char*)pal, (const char*)pbh,
            fcb + (size_t)l * 4 * DD, nullptr, pfh, pfl, MTOK, 4 * DD, DD);
        // --- cproj (+residual) ---
        cvt_w<<<DD * 4 * DD / 1024, 256>>>(cprojw + (size_t)l * DD * 4 * DD, pbh, DD * 4 * DD / 4);
        gemm_bf<2><<<dim3(DD / 128, MTOK / 128), 256, GEMM_SMEM>>>(
            (const char*)pfh, (const char*)pfl, (const char*)pbh,
            cprojb + (size_t)l * DD, px, nullptr, nullptr, MTOK, DD, 4 * DD);
    }

    ln_k<<<MTOK, 256>>>(px, lnfw, lnfb, pah, pal);
    cvt_w<<<VV * DD / 1024, 256>>>(headw, pbh, VV * DD / 4);
    gemm_bf<3><<<dim3(VV / 128, MTOK / 128), 256, GEMM_SMEM>>>(
        (const char*)pah, (const char*)pal, (const char*)pbh,
        nullptr, out, nullptr, nullptr, MTOK, VV, DD);
}